// round 7
// baseline (speedup 1.0000x reference)
#include <cuda_runtime.h>
#include <stdint.h>

#define NN 1000000
#define NE 10000000
#define HID 8
#define NG 64
#define NW 31250

#define CE_IDX 4096
#define CE4    32768
#define CE3    262144
#define CL4    4096
#define CL3    32768
#define CL2    262144

// ---- device scratch ----
__device__ int      g_is64;
__device__ int      g_deg[NN];
__device__ float    g_dinv[NN];
__device__ int4     g_pk[NE / 2];         // packed edges: {s0,d0,s1,d1}
__device__ float    g_agg1[NN];           // scalar layer-1 aggregate (S2 rows)
__device__ float    g_agga[NN * HID];     // layer-3 aggregate (S3 rows)
__device__ float    g_aggb[NN * HID];     // layer-4 aggregate (S4 rows)
__device__ float    g_v1[NN * HID];       // g3
__device__ float    g_v2[NN * HID];       // g2 then g4
__device__ unsigned g_bm_idx[NW], g_bm4[NW], g_bm3[NW], g_bm2[NW];
__device__ int2     g_eidx[CE_IDX], g_e4[CE4], g_e3[CE3];
__device__ int      g_l4[CL4], g_l3[CL3], g_l2[CL2];
__device__ int      g_ceidx, g_ce4, g_ce3, g_cl4, g_cl3, g_cl2;

__device__ __forceinline__ bool bm_test(const unsigned* bm, int i) {
    return (bm[i >> 5] >> (i & 31)) & 1u;
}
__device__ __forceinline__ bool bm_claim(unsigned* bm, int i) {
    unsigned old = atomicOr(&bm[i >> 5], 1u << (i & 31));
    return !((old >> (i & 31)) & 1u);
}

__global__ void k_detect(const void* __restrict__ ei_raw) {
    const int* w = (const int*)ei_raw;
    int zeros = 0;
    for (int i = 1; i < 128; i += 2)
        if (w[i] == 0) zeros++;
    g_is64 = (zeros >= 48) ? 1 : 0;
}

__global__ void k_init() {
    int i = blockIdx.x * blockDim.x + threadIdx.x;
    int stride = gridDim.x * blockDim.x;
    for (int k = i; k < NN; k += stride) g_deg[k] = 0;
    for (int k = i; k < NW; k += stride) {
        g_bm_idx[k] = 0; g_bm4[k] = 0; g_bm3[k] = 0; g_bm2[k] = 0;
    }
    if (i == 0) {
        g_ceidx = 0; g_ce4 = 0; g_ce3 = 0;
        g_cl4 = 0; g_cl3 = 0; g_cl2 = 0;
    }
}

// seed: mark bm_idx; claim idx into bm4/l4; zero agg_b rows
__global__ void k_seed0(const void* __restrict__ idx_raw) {
    int k = threadIdx.x;
    if (k >= NG) return;
    int n = g_is64 ? (int)((const long long*)idx_raw)[k]
                   : ((const int*)idx_raw)[k];
    bm_claim(g_bm_idx, n);
    if (bm_claim(g_bm4, n)) {
        int p = atomicAdd(&g_cl4, 1);
        if (p < CL4) g_l4[p] = n;
        float* ab = g_aggb + (size_t)n * HID;
        #pragma unroll
        for (int j = 0; j < HID; j++) ab[j] = 0.f;
    }
}

// P1: read int64/int32 edges (2/thread), pack int4, degree, capture dst-in-idx
__global__ void k_p1(const void* __restrict__ ei_raw) {
    __shared__ int2 ebuf[512];
    __shared__ int  nbuf[512];
    __shared__ int  ecnt, ncnt, ebase, nbase;
    if (threadIdx.x == 0) { ecnt = 0; ncnt = 0; }
    __syncthreads();
    int i = blockIdx.x * blockDim.x + threadIdx.x;   // edge pair index
    int s0, d0, s1, d1;
    bool valid = (i < NE / 2);
    if (valid) {
        if (g_is64) {
            longlong2 sp = ((const longlong2*)ei_raw)[i];
            longlong2 dp = ((const longlong2*)ei_raw)[NE / 2 + i];
            s0 = (int)sp.x; s1 = (int)sp.y;
            d0 = (int)dp.x; d1 = (int)dp.y;
        } else {
            int2 sp = ((const int2*)ei_raw)[i];
            int2 dp = ((const int2*)ei_raw)[NE / 2 + i];
            s0 = sp.x; s1 = sp.y;
            d0 = dp.x; d1 = dp.y;
        }
        g_pk[i] = make_int4(s0, d0, s1, d1);
        atomicAdd(&g_deg[d0], 1);
        atomicAdd(&g_deg[d1], 1);
        if (bm_test(g_bm_idx, d0)) {
            int p = atomicAdd(&ecnt, 1); ebuf[p] = make_int2(s0, d0);
            if (bm_claim(g_bm4, s0)) { int q = atomicAdd(&ncnt, 1); nbuf[q] = s0; }
        }
        if (bm_test(g_bm_idx, d1)) {
            int p = atomicAdd(&ecnt, 1); ebuf[p] = make_int2(s1, d1);
            if (bm_claim(g_bm4, s1)) { int q = atomicAdd(&ncnt, 1); nbuf[q] = s1; }
        }
    }
    __syncthreads();
    if (threadIdx.x == 0) {
        ebase = ecnt ? atomicAdd(&g_ceidx, ecnt) : 0;
        nbase = ncnt ? atomicAdd(&g_cl4, ncnt) : 0;
    }
    __syncthreads();
    for (int t = threadIdx.x; t < ecnt; t += blockDim.x)
        if (ebase + t < CE_IDX) g_eidx[ebase + t] = ebuf[t];
    for (int t = threadIdx.x; t < ncnt; t += blockDim.x)
        if (nbase + t < CL4) {
            int n = nbuf[t];
            g_l4[nbase + t] = n;
            float* ab = g_aggb + (size_t)n * HID;
            #pragma unroll
            for (int j = 0; j < HID; j++) ab[j] = 0.f;
        }
}

__global__ void k_dinv() {
    int i = blockIdx.x * blockDim.x + threadIdx.x;
    if (i < NN) g_dinv[i] = rsqrtf((float)g_deg[i] + 1.0f);
}

// copy l4 into bm3/l3 (zero agg_a)
__global__ void k_seed34() {
    int i = blockIdx.x * blockDim.x + threadIdx.x;
    if (i >= min(g_cl4, CL4)) return;
    int n = g_l4[i];
    if (bm_claim(g_bm3, n)) {
        int p = atomicAdd(&g_cl3, 1);
        if (p < CL3) g_l3[p] = n;
        float* aa = g_agga + (size_t)n * HID;
        #pragma unroll
        for (int j = 0; j < HID; j++) aa[j] = 0.f;
    }
}

// P2: dst in bm4 -> capture E4, claim bm3[src] (l3, zero agg_a)
__global__ void k_p2() {
    __shared__ int2 ebuf[512];
    __shared__ int  nbuf[512];
    __shared__ int  ecnt, ncnt, ebase, nbase;
    if (threadIdx.x == 0) { ecnt = 0; ncnt = 0; }
    __syncthreads();
    int i = blockIdx.x * blockDim.x + threadIdx.x;
    if (i < NE / 2) {
        int4 e = g_pk[i];
        if (bm_test(g_bm4, e.y)) {
            int p = atomicAdd(&ecnt, 1); ebuf[p] = make_int2(e.x, e.y);
            if (bm_claim(g_bm3, e.x)) { int q = atomicAdd(&ncnt, 1); nbuf[q] = e.x; }
        }
        if (bm_test(g_bm4, e.w)) {
            int p = atomicAdd(&ecnt, 1); ebuf[p] = make_int2(e.z, e.w);
            if (bm_claim(g_bm3, e.z)) { int q = atomicAdd(&ncnt, 1); nbuf[q] = e.z; }
        }
    }
    __syncthreads();
    if (threadIdx.x == 0) {
        ebase = ecnt ? atomicAdd(&g_ce4, ecnt) : 0;
        nbase = ncnt ? atomicAdd(&g_cl3, ncnt) : 0;
    }
    __syncthreads();
    for (int t = threadIdx.x; t < ecnt; t += blockDim.x)
        if (ebase + t < CE4) g_e4[ebase + t] = ebuf[t];
    for (int t = threadIdx.x; t < ncnt; t += blockDim.x)
        if (nbase + t < CL3) {
            int n = nbuf[t];
            g_l3[nbase + t] = n;
            float* aa = g_agga + (size_t)n * HID;
            #pragma unroll
            for (int j = 0; j < HID; j++) aa[j] = 0.f;
        }
}

// copy l3 into bm2/l2 (zero agg1)
__global__ void k_seed23() {
    int i = blockIdx.x * blockDim.x + threadIdx.x;
    if (i >= min(g_cl3, CL3)) return;
    int n = g_l3[i];
    if (bm_claim(g_bm2, n)) {
        int p = atomicAdd(&g_cl2, 1);
        if (p < CL2) g_l2[p] = n;
        g_agg1[n] = 0.f;
    }
}

// P3: dst in bm3 -> capture E3, claim bm2[src] (l2, zero agg1)
__global__ void k_p3() {
    __shared__ int2 ebuf[512];
    __shared__ int  nbuf[512];
    __shared__ int  ecnt, ncnt, ebase, nbase;
    if (threadIdx.x == 0) { ecnt = 0; ncnt = 0; }
    __syncthreads();
    int i = blockIdx.x * blockDim.x + threadIdx.x;
    if (i < NE / 2) {
        int4 e = g_pk[i];
        if (bm_test(g_bm3, e.y)) {
            int p = atomicAdd(&ecnt, 1); ebuf[p] = make_int2(e.x, e.y);
            if (bm_claim(g_bm2, e.x)) { int q = atomicAdd(&ncnt, 1); nbuf[q] = e.x; }
        }
        if (bm_test(g_bm3, e.w)) {
            int p = atomicAdd(&ecnt, 1); ebuf[p] = make_int2(e.z, e.w);
            if (bm_claim(g_bm2, e.z)) { int q = atomicAdd(&ncnt, 1); nbuf[q] = e.z; }
        }
    }
    __syncthreads();
    if (threadIdx.x == 0) {
        ebase = ecnt ? atomicAdd(&g_ce3, ecnt) : 0;
        nbase = ncnt ? atomicAdd(&g_cl2, ncnt) : 0;
    }
    __syncthreads();
    for (int t = threadIdx.x; t < ecnt; t += blockDim.x)
        if (ebase + t < CE3) g_e3[ebase + t] = ebuf[t];
    for (int t = threadIdx.x; t < ncnt; t += blockDim.x)
        if (nbase + t < CL2) {
            int n = nbuf[t];
            g_l2[nbase + t] = n;
            g_agg1[n] = 0.f;
        }
}

// P4: dst in bm2 -> agg1[dst] += x[src]*dinv[src]  (scalar layer-1 agg)
__global__ void k_p4(const float* __restrict__ x) {
    int i = blockIdx.x * blockDim.x + threadIdx.x;
    if (i >= NE / 2) return;
    int4 e = g_pk[i];
    if (bm_test(g_bm2, e.y))
        atomicAdd(&g_agg1[e.y], x[e.x] * g_dinv[e.x]);
    if (bm_test(g_bm2, e.w))
        atomicAdd(&g_agg1[e.w], x[e.z] * g_dinv[e.z]);
}

// layer 1+2 at S2: g2 = (relu(dinv*(agg1 + x*dinv)*W1 + b1) @ W2) * dinv -> v2
__global__ void k_layer2(const float* __restrict__ x,
                         const float* __restrict__ W1,
                         const float* __restrict__ b1,
                         const float* __restrict__ W2) {
    int i = blockIdx.x * blockDim.x + threadIdx.x;
    if (i >= min(g_cl2, CL2)) return;
    int d = g_l2[i];
    float dinv = g_dinv[d];
    float pre = dinv * (g_agg1[d] + x[d] * dinv);
    float h[HID];
    #pragma unroll
    for (int j = 0; j < HID; j++)
        h[j] = fmaxf(pre * __ldg(&W1[j]) + __ldg(&b1[j]), 0.f);
    float* g2 = g_v2 + (size_t)d * HID;
    #pragma unroll
    for (int j = 0; j < HID; j++) {
        float acc = 0.f;
        #pragma unroll
        for (int k = 0; k < HID; k++)
            acc = fmaf(h[k], __ldg(&W2[k * HID + j]), acc);
        g2[j] = acc * dinv;
    }
}

// edge-list aggregate: agg[dst] += gsrc[src] (8 float atomics)
__global__ void k_eagg(int which) {   // 3: E3/v2->agga ; 4: E4/v1->aggb
    int i = blockIdx.x * blockDim.x + threadIdx.x;
    int n = (which == 3) ? min(g_ce3, CE3) : min(g_ce4, CE4);
    if (i >= n) return;
    int2 sd = (which == 3) ? g_e3[i] : g_e4[i];
    const float* gs = ((which == 3) ? g_v2 : g_v1) + (size_t)sd.x * HID;
    float* ad = ((which == 3) ? g_agga : g_aggb) + (size_t)sd.y * HID;
    #pragma unroll
    for (int j = 0; j < HID; j++) atomicAdd(ad + j, gs[j]);
}

// node transform: which=3: l3, gin=v2+agga, gout=v1 (W3,b2)
//                 which=4: l4, gin=v1+aggb, gout=v2 (W4,b3)
__global__ void k_node(int which,
                       const float* __restrict__ W,
                       const float* __restrict__ b) {
    int i = blockIdx.x * blockDim.x + threadIdx.x;
    int n = (which == 3) ? min(g_cl3, CL3) : min(g_cl4, CL4);
    if (i >= n) return;
    int d = (which == 3) ? g_l3[i] : g_l4[i];
    const float* gin = ((which == 3) ? g_v2 : g_v1) + (size_t)d * HID;
    const float* ag  = ((which == 3) ? g_agga : g_aggb) + (size_t)d * HID;
    float* gout      = ((which == 3) ? g_v1 : g_v2) + (size_t)d * HID;
    float dinv = g_dinv[d];
    float h[HID];
    #pragma unroll
    for (int j = 0; j < HID; j++)
        h[j] = fmaxf(dinv * (ag[j] + gin[j]) + __ldg(&b[j]), 0.f);
    #pragma unroll
    for (int j = 0; j < HID; j++) {
        float a = 0.f;
        #pragma unroll
        for (int k = 0; k < HID; k++)
            a = fmaf(h[k], __ldg(&W[k * HID + j]), a);
        gout[j] = a * dinv;
    }
}

// final: per output k, scan E_idx for dst==node, sum g4[src]; add self
__global__ void k_final(const void* __restrict__ idx_raw,
                        const float* __restrict__ b4,
                        float* __restrict__ out) {
    int k = threadIdx.x;
    if (k >= NG) return;
    int d = g_is64 ? (int)((const long long*)idx_raw)[k]
                   : ((const int*)idx_raw)[k];
    float acc8[HID];
    const float* gd = g_v2 + (size_t)d * HID;
    #pragma unroll
    for (int j = 0; j < HID; j++) acc8[j] = gd[j];
    int n = min(g_ceidx, CE_IDX);
    for (int e = 0; e < n; e++) {
        int2 sd = g_eidx[e];
        if (sd.y == d) {
            const float* gs = g_v2 + (size_t)sd.x * HID;
            #pragma unroll
            for (int j = 0; j < HID; j++) acc8[j] += gs[j];
        }
    }
    float dinv = g_dinv[d];
    #pragma unroll
    for (int j = 0; j < HID; j++)
        out[k * HID + j] = dinv * acc8[j] + __ldg(&b4[j]);
}

extern "C" void kernel_launch(void* const* d_in, const int* in_sizes, int n_in,
                              void* d_out, int out_size) {
    const float* x  = (const float*)d_in[0];
    const void*  ei = d_in[1];
    const void*  idx = d_in[2];
    const float* W1 = (const float*)d_in[3];
    const float* b1 = (const float*)d_in[4];
    const float* W2 = (const float*)d_in[5];
    const float* b2 = (const float*)d_in[6];
    const float* W3 = (const float*)d_in[7];
    const float* b3 = (const float*)d_in[8];
    const float* W4 = (const float*)d_in[9];
    const float* b4 = (const float*)d_in[10];
    float* out = (float*)d_out;

    const int TB = 256;
    int nbP = (NE / 2 + TB - 1) / TB;     // edge-pair grid
    int nbN = (NN + TB - 1) / TB;

    k_detect<<<1, 1>>>(ei);
    k_init<<<1024, TB>>>();
    k_seed0<<<1, 64>>>(idx);
    k_p1<<<nbP, TB>>>(ei);                // pack + deg + E_idx + S4
    k_dinv<<<nbN, TB>>>();
    k_seed34<<<CL4 / TB, TB>>>();
    k_p2<<<nbP, TB>>>();                  // E4 + S3
    k_seed23<<<CL3 / TB, TB>>>();
    k_p3<<<nbP, TB>>>();                  // E3 + S2
    k_p4<<<nbP, TB>>>(x);                 // scalar layer-1 agg at S2
    k_layer2<<<CL2 / TB, TB>>>(x, W1, b1, W2);
    k_eagg<<<CE3 / TB, TB>>>(3);
    k_node<<<CL3 / TB, TB>>>(3, W3, b2);
    k_eagg<<<CE4 / TB, TB>>>(4);
    k_node<<<CL4 / TB, TB>>>(4, W4, b3);
    k_final<<<1, 64>>>(idx, b4, out);
}

// round 8
// speedup vs baseline: 1.0779x; 1.0779x over previous
#include <cuda_runtime.h>
#include <stdint.h>

#define NN 1000000
#define NE 10000000
#define HID 8
#define NG 64
#define NW 31250

#define CE_IDX 8192
#define CE4    65536
#define CE3    524288
#define CL4    8192
#define CL3    65536
#define CL2    524288
#define BUF    256

// ---- device scratch ----
__device__ int      g_is64;
__device__ int      g_deg[NN];
__device__ float    g_dinv[NN];
__device__ int      g_dst[NE];            // dst-only packed stream (40 MB)
__device__ float    g_agg1[NN];           // scalar layer-1 aggregate
__device__ float    g_agga[NN * HID];     // layer-3 aggregate
__device__ float    g_aggb[NN * HID];     // layer-4 aggregate
__device__ float    g_v1[NN * HID];       // g3
__device__ float    g_v2[NN * HID];       // g2 then g4
__device__ unsigned g_bm_idx[NW], g_bm4[NW], g_bm3[NW], g_bm2[NW];
__device__ int2     g_eidx[CE_IDX], g_e4[CE4], g_e3[CE3];
__device__ int      g_l4[CL4], g_l3[CL3], g_l2[CL2];
__device__ int      g_ceidx, g_ce4, g_ce3, g_cl4, g_cl3, g_cl2;

__device__ __forceinline__ bool bm_test(const unsigned* bm, int i) {
    return (bm[i >> 5] >> (i & 31)) & 1u;
}
__device__ __forceinline__ bool bm_claim(unsigned* bm, int i) {
    unsigned old = atomicOr(&bm[i >> 5], 1u << (i & 31));
    return !((old >> (i & 31)) & 1u);
}
// lazy src fetch from the original edge buffer
__device__ __forceinline__ int load_src(const void* ei_raw, int e) {
    return g_is64 ? (int)((const long long*)ei_raw)[e]
                  : ((const int*)ei_raw)[e];
}
__device__ __forceinline__ void zero_row(float* p) {
    float4 z = make_float4(0.f, 0.f, 0.f, 0.f);
    ((float4*)p)[0] = z; ((float4*)p)[1] = z;
}

__global__ void k_detect(const void* __restrict__ ei_raw) {
    const int* w = (const int*)ei_raw;
    int zeros = 0;
    for (int i = 1; i < 128; i += 2)
        if (w[i] == 0) zeros++;
    g_is64 = (zeros >= 48) ? 1 : 0;
}

__global__ void k_init() {
    int i = blockIdx.x * blockDim.x + threadIdx.x;
    int stride = gridDim.x * blockDim.x;
    for (int k = i; k < NN; k += stride) g_deg[k] = 0;
    for (int k = i; k < NW; k += stride) {
        g_bm_idx[k] = 0; g_bm4[k] = 0; g_bm3[k] = 0; g_bm2[k] = 0;
    }
    if (i == 0) {
        g_ceidx = 0; g_ce4 = 0; g_ce3 = 0;
        g_cl4 = 0; g_cl3 = 0; g_cl2 = 0;
    }
}

__global__ void k_seed0(const void* __restrict__ idx_raw) {
    int k = threadIdx.x;
    if (k >= NG) return;
    int n = g_is64 ? (int)((const long long*)idx_raw)[k]
                   : ((const int*)idx_raw)[k];
    bm_claim(g_bm_idx, n);
    if (bm_claim(g_bm4, n)) {
        int p = atomicAdd(&g_cl4, 1);
        g_l4[p] = n;
        zero_row(g_aggb + (size_t)n * HID);
    }
}

// P1: read edges (2/thread), write dst32, degree REDG, capture dst-in-idx + S4
__global__ void k_p1(const void* __restrict__ ei_raw) {
    __shared__ int2 ebuf[BUF];
    __shared__ int  nbuf[BUF];
    __shared__ int  ecnt, ncnt, ebase, nbase;
    if (threadIdx.x == 0) { ecnt = 0; ncnt = 0; }
    __syncthreads();
    int i = blockIdx.x * blockDim.x + threadIdx.x;   // edge-pair index
    if (i < NE / 2) {
        int d0, d1;
        if (g_is64) {
            longlong2 dp = ((const longlong2*)ei_raw)[NE / 2 + i];
            d0 = (int)dp.x; d1 = (int)dp.y;
        } else {
            int2 dp = ((const int2*)ei_raw)[NE / 2 + i];
            d0 = dp.x; d1 = dp.y;
        }
        ((int2*)g_dst)[i] = make_int2(d0, d1);
        atomicAdd(&g_deg[d0], 1);
        atomicAdd(&g_deg[d1], 1);
        if (bm_test(g_bm_idx, d0)) {
            int s = load_src(ei_raw, 2 * i);
            int p = atomicAdd(&ecnt, 1);
            if (p < BUF) ebuf[p] = make_int2(s, d0);
            else { int q = atomicAdd(&g_ceidx, 1); g_eidx[q] = make_int2(s, d0); }
            if (bm_claim(g_bm4, s)) {
                int q = atomicAdd(&ncnt, 1);
                if (q < BUF) nbuf[q] = s;
                else { int r = atomicAdd(&g_cl4, 1); g_l4[r] = s; zero_row(g_aggb + (size_t)s * HID); }
            }
        }
        if (bm_test(g_bm_idx, d1)) {
            int s = load_src(ei_raw, 2 * i + 1);
            int p = atomicAdd(&ecnt, 1);
            if (p < BUF) ebuf[p] = make_int2(s, d1);
            else { int q = atomicAdd(&g_ceidx, 1); g_eidx[q] = make_int2(s, d1); }
            if (bm_claim(g_bm4, s)) {
                int q = atomicAdd(&ncnt, 1);
                if (q < BUF) nbuf[q] = s;
                else { int r = atomicAdd(&g_cl4, 1); g_l4[r] = s; zero_row(g_aggb + (size_t)s * HID); }
            }
        }
    }
    __syncthreads();
    int ec = min(ecnt, BUF), nc = min(ncnt, BUF);
    if (threadIdx.x == 0) {
        ebase = ec ? atomicAdd(&g_ceidx, ec) : 0;
        nbase = nc ? atomicAdd(&g_cl4, nc) : 0;
    }
    __syncthreads();
    for (int t = threadIdx.x; t < ec; t += blockDim.x)
        g_eidx[ebase + t] = ebuf[t];
    for (int t = threadIdx.x; t < nc; t += blockDim.x) {
        int n = nbuf[t];
        g_l4[nbase + t] = n;
        zero_row(g_aggb + (size_t)n * HID);
    }
}

__global__ void k_dinv() {
    int i = blockIdx.x * blockDim.x + threadIdx.x;
    if (i < NN) g_dinv[i] = rsqrtf((float)g_deg[i] + 1.0f);
}

// copy l4 into bm3/l3 (zero agga)
__global__ void k_seed34() {
    int i = blockIdx.x * blockDim.x + threadIdx.x;
    if (i >= min(g_cl4, CL4)) return;
    int n = g_l4[i];
    if (bm_claim(g_bm3, n)) {
        int p = atomicAdd(&g_cl3, 1);
        g_l3[p] = n;
        zero_row(g_agga + (size_t)n * HID);
    }
}

// generic expansion scan over dst32 (4 edges/thread):
// stage 2: dst in bm4 -> E4, claim bm3 (agga zero)
// stage 3: dst in bm3 -> E3, claim bm2 (agg1 zero)
__global__ void k_scan(const void* __restrict__ ei_raw, int stage) {
    __shared__ int2 ebuf[BUF];
    __shared__ int  nbuf[BUF];
    __shared__ int  ecnt, ncnt, ebase, nbase;
    if (threadIdx.x == 0) { ecnt = 0; ncnt = 0; }
    __syncthreads();
    const unsigned* bm_in = (stage == 2) ? g_bm4 : g_bm3;
    unsigned* bm_out      = (stage == 2) ? g_bm3 : g_bm2;
    int2* elist           = (stage == 2) ? g_e4 : g_e3;
    int*  ecounter        = (stage == 2) ? &g_ce4 : &g_ce3;
    int*  nlist           = (stage == 2) ? g_l3 : g_l2;
    int*  ncounter        = (stage == 2) ? &g_cl3 : &g_cl2;
    int i = blockIdx.x * blockDim.x + threadIdx.x;
    if (i < NE / 4) {
        int4 d4 = ((const int4*)g_dst)[i];
        int ds[4] = {d4.x, d4.y, d4.z, d4.w};
        #pragma unroll
        for (int k = 0; k < 4; k++) {
            int d = ds[k];
            if (bm_test(bm_in, d)) {
                int e = 4 * i + k;
                int s = load_src(ei_raw, e);
                int p = atomicAdd(&ecnt, 1);
                if (p < BUF) ebuf[p] = make_int2(s, d);
                else { int q = atomicAdd(ecounter, 1); elist[q] = make_int2(s, d); }
                if (bm_claim(bm_out, s)) {
                    int q = atomicAdd(&ncnt, 1);
                    if (q < BUF) nbuf[q] = s;
                    else {
                        int r = atomicAdd(ncounter, 1);
                        nlist[r] = s;
                        if (stage == 2) zero_row(g_agga + (size_t)s * HID);
                        else            g_agg1[s] = 0.f;
                    }
                }
            }
        }
    }
    __syncthreads();
    int ec = min(ecnt, BUF), nc = min(ncnt, BUF);
    if (threadIdx.x == 0) {
        ebase = ec ? atomicAdd(ecounter, ec) : 0;
        nbase = nc ? atomicAdd(ncounter, nc) : 0;
    }
    __syncthreads();
    for (int t = threadIdx.x; t < ec; t += blockDim.x)
        elist[ebase + t] = ebuf[t];
    for (int t = threadIdx.x; t < nc; t += blockDim.x) {
        int n = nbuf[t];
        nlist[nbase + t] = n;
        if (stage == 2) zero_row(g_agga + (size_t)n * HID);
        else            g_agg1[n] = 0.f;
    }
}

// copy l3 into bm2/l2 (zero agg1)
__global__ void k_seed23() {
    int i = blockIdx.x * blockDim.x + threadIdx.x;
    if (i >= min(g_cl3, CL3)) return;
    int n = g_l3[i];
    if (bm_claim(g_bm2, n)) {
        int p = atomicAdd(&g_cl2, 1);
        g_l2[p] = n;
        g_agg1[n] = 0.f;
    }
}

// P4: dst in bm2 -> agg1[dst] += x[src]*dinv[src]
__global__ void k_p4(const void* __restrict__ ei_raw, const float* __restrict__ x) {
    int i = blockIdx.x * blockDim.x + threadIdx.x;
    if (i >= NE / 4) return;
    int4 d4 = ((const int4*)g_dst)[i];
    int ds[4] = {d4.x, d4.y, d4.z, d4.w};
    #pragma unroll
    for (int k = 0; k < 4; k++) {
        int d = ds[k];
        if (bm_test(g_bm2, d)) {
            int s = load_src(ei_raw, 4 * i + k);
            atomicAdd(&g_agg1[d], x[s] * g_dinv[s]);
        }
    }
}

// layer 1+2 at S2: g2 = (relu(dinv*(agg1 + x*dinv)*W1 + b1) @ W2) * dinv -> v2
__global__ void k_layer2(const float* __restrict__ x,
                         const float* __restrict__ W1,
                         const float* __restrict__ b1,
                         const float* __restrict__ W2) {
    int i = blockIdx.x * blockDim.x + threadIdx.x;
    if (i >= min(g_cl2, CL2)) return;
    int d = g_l2[i];
    float dinv = g_dinv[d];
    float pre = dinv * (g_agg1[d] + x[d] * dinv);
    float h[HID];
    #pragma unroll
    for (int j = 0; j < HID; j++)
        h[j] = fmaxf(pre * __ldg(&W1[j]) + __ldg(&b1[j]), 0.f);
    float* g2 = g_v2 + (size_t)d * HID;
    #pragma unroll
    for (int j = 0; j < HID; j++) {
        float acc = 0.f;
        #pragma unroll
        for (int k = 0; k < HID; k++)
            acc = fmaf(h[k], __ldg(&W2[k * HID + j]), acc);
        g2[j] = acc * dinv;
    }
}

// edge-list aggregate: agg[dst] += gsrc[src]
__global__ void k_eagg(int which) {   // 3: E3/v2->agga ; 4: E4/v1->aggb
    int i = blockIdx.x * blockDim.x + threadIdx.x;
    int n = (which == 3) ? min(g_ce3, CE3) : min(g_ce4, CE4);
    if (i >= n) return;
    int2 sd = (which == 3) ? g_e3[i] : g_e4[i];
    const float* gs = ((which == 3) ? g_v2 : g_v1) + (size_t)sd.x * HID;
    float* ad = ((which == 3) ? g_agga : g_aggb) + (size_t)sd.y * HID;
    #pragma unroll
    for (int j = 0; j < HID; j++) atomicAdd(ad + j, gs[j]);
}

// node transform: which=3: l3, gin=v2+agga, gout=v1 (W3,b2)
//                 which=4: l4, gin=v1+aggb, gout=v2 (W4,b3)
__global__ void k_node(int which,
                       const float* __restrict__ W,
                       const float* __restrict__ b) {
    int i = blockIdx.x * blockDim.x + threadIdx.x;
    int n = (which == 3) ? min(g_cl3, CL3) : min(g_cl4, CL4);
    if (i >= n) return;
    int d = (which == 3) ? g_l3[i] : g_l4[i];
    const float* gin = ((which == 3) ? g_v2 : g_v1) + (size_t)d * HID;
    const float* ag  = ((which == 3) ? g_agga : g_aggb) + (size_t)d * HID;
    float* gout      = ((which == 3) ? g_v1 : g_v2) + (size_t)d * HID;
    float dinv = g_dinv[d];
    float h[HID];
    #pragma unroll
    for (int j = 0; j < HID; j++)
        h[j] = fmaxf(dinv * (ag[j] + gin[j]) + __ldg(&b[j]), 0.f);
    #pragma unroll
    for (int j = 0; j < HID; j++) {
        float a = 0.f;
        #pragma unroll
        for (int k = 0; k < HID; k++)
            a = fmaf(h[k], __ldg(&W[k * HID + j]), a);
        gout[j] = a * dinv;
    }
}

// final: per output k, scan E_idx for dst==node, sum g4[src]; add self
__global__ void k_final(const void* __restrict__ idx_raw,
                        const float* __restrict__ b4,
                        float* __restrict__ out) {
    int k = threadIdx.x;
    if (k >= NG) return;
    int d = g_is64 ? (int)((const long long*)idx_raw)[k]
                   : ((const int*)idx_raw)[k];
    float acc8[HID];
    const float* gd = g_v2 + (size_t)d * HID;
    #pragma unroll
    for (int j = 0; j < HID; j++) acc8[j] = gd[j];
    int n = min(g_ceidx, CE_IDX);
    for (int e = 0; e < n; e++) {
        int2 sd = g_eidx[e];
        if (sd.y == d) {
            const float* gs = g_v2 + (size_t)sd.x * HID;
            #pragma unroll
            for (int j = 0; j < HID; j++) acc8[j] += gs[j];
        }
    }
    float dinv = g_dinv[d];
    #pragma unroll
    for (int j = 0; j < HID; j++)
        out[k * HID + j] = dinv * acc8[j] + __ldg(&b4[j]);
}

extern "C" void kernel_launch(void* const* d_in, const int* in_sizes, int n_in,
                              void* d_out, int out_size) {
    const float* x  = (const float*)d_in[0];
    const void*  ei = d_in[1];
    const void*  idx = d_in[2];
    const float* W1 = (const float*)d_in[3];
    const float* b1 = (const float*)d_in[4];
    const float* W2 = (const float*)d_in[5];
    const float* b2 = (const float*)d_in[6];
    const float* W3 = (const float*)d_in[7];
    const float* b3 = (const float*)d_in[8];
    const float* W4 = (const float*)d_in[9];
    const float* b4 = (const float*)d_in[10];
    float* out = (float*)d_out;

    const int TB = 256;
    int nbP = (NE / 2 + TB - 1) / TB;     // edge-pair grid
    int nbQ = (NE / 4 + TB - 1) / TB;     // edge-quad grid
    int nbN = (NN + TB - 1) / TB;

    k_detect<<<1, 1>>>(ei);
    k_init<<<1024, TB>>>();
    k_seed0<<<1, 64>>>(idx);
    k_p1<<<nbP, TB>>>(ei);                 // dst32 + deg + E_idx + S4
    k_dinv<<<nbN, TB>>>();
    k_seed34<<<CL4 / TB, TB>>>();
    k_scan<<<nbQ, TB>>>(ei, 2);            // E4 + S3
    k_seed23<<<CL3 / TB, TB>>>();
    k_scan<<<nbQ, TB>>>(ei, 3);            // E3 + S2
    k_p4<<<nbQ, TB>>>(ei, x);              // scalar layer-1 agg at S2
    k_layer2<<<CL2 / TB, TB>>>(x, W1, b1, W2);
    k_eagg<<<CE3 / TB, TB>>>(3);
    k_node<<<CL3 / TB, TB>>>(3, W3, b2);
    k_eagg<<<CE4 / TB, TB>>>(4);
    k_node<<<CL4 / TB, TB>>>(4, W4, b3);
    k_final<<<1, 64>>>(idx, b4, out);
}